// round 17
// baseline (speedup 1.0000x reference)
#include <cuda_runtime.h>
#include <cstdint>
#include <math.h>

#define BB 64
#define TMAX 256
#define PP 64
#define DD 128
#define CC 10
#define TBASE 367

// Scratch (no cudaMalloc allowed)
__device__ int    d_len[BB];
__device__ int    d_off[BB + 1];
__device__ float  d_E[TBASE * CC];            // E[date*C + c]
__device__ float4 d_Y4[BB * CC * (PP / 4)];   // Y[b][c][p] as float4 along p

// Compact setup partition (175 blocks x 256 thr = 45K threads)
#define NB_Y    128                 // blocks 0..127: Y (each warp: 4 (b,p) units)
#define NB_E    46                  // blocks 128..173: E (8 dates per block, warp-per-date)
#define BID_LEN (NB_Y + NB_E)       // block 174: lengths + prefix sum
#define NB_SETUP (BID_LEN + 1)      // 175

// -log2(TBASE)/64 for inv_freq = TBASE^(-2k/D) = 2^(k * NEG_L2B_64)
#define NEG_L2B_64 (-0.1331193181f)

// ---------------------------------------------------------------------------
// Compact setup kernel: Y precompute + E table + ragged lengths/offsets.
// ---------------------------------------------------------------------------
__global__ void __launch_bounds__(256) k_setup(const float* __restrict__ x,
                                               const int*   __restrict__ dates,
                                               const float* __restrict__ W,
                                               const float* __restrict__ bias) {
    int bid = blockIdx.x;
    int tid = threadIdx.x;
    int wid  = tid >> 5;
    int lane = tid & 31;

    if (bid < NB_Y) {
        // ---- Y[b][c][p] = bias[c] + x[b,p,:] . W[c,:]
        // One warp handles 4 consecutive (b,p) units (MLP-4 x loads).
        int u0 = (bid * 8 + wid) * 4;            // first (b,p) unit

        const float4* x4 = (const float4*)x;
        const float4* W4 = (const float4*)W;
        float* Yf = (float*)d_Y4;

        float4 xv[4];
        #pragma unroll
        for (int i = 0; i < 4; ++i)
            xv[i] = x4[(size_t)(u0 + i) * (DD / 4) + lane];   // x[b,p,:] rows

        #pragma unroll
        for (int c = 0; c < CC; ++c) {
            float4 wv = W4[c * (DD / 4) + lane];
            float v[4];
            #pragma unroll
            for (int i = 0; i < 4; ++i)
                v[i] = fmaf(xv[i].x, wv.x, fmaf(xv[i].y, wv.y,
                       fmaf(xv[i].z, wv.z, xv[i].w * wv.w)));
            #pragma unroll
            for (int o = 16; o > 0; o >>= 1) {
                #pragma unroll
                for (int i = 0; i < 4; ++i)     // 4 independent chains pipeline
                    v[i] += __shfl_down_sync(0xffffffffu, v[i], o);
            }
            if (lane == 0) {
                #pragma unroll
                for (int i = 0; i < 4; ++i) {
                    int u = u0 + i;
                    int b = u >> 6, p = u & 63;
                    Yf[(b * CC + c) * PP + p] = v[i] + bias[c];
                }
            }
        }
    } else if (bid < BID_LEN) {
        // ---- E[pos,c] = sinusoid_table[pos,:] . W[c,:], warp-per-date.
        // Lane l covers frequency pairs k = l and k = l + 32.
        int pos = (bid - NB_Y) * 8 + wid;
        if (pos < TBASE) {
            float if1 = exp2f((float)lane * NEG_L2B_64);
            float if2 = exp2f((float)(lane + 32) * NEG_L2B_64);
            float s1, c1, s2, c2;
            sincosf((float)pos * if1, &s1, &c1);
            sincosf((float)pos * if2, &s2, &c2);

            const float2* W2 = (const float2*)W;   // W2[c*64 + k] = (W[c,2k], W[c,2k+1])
            #pragma unroll
            for (int c = 0; c < CC; ++c) {
                float2 wa = W2[c * 64 + lane];
                float2 wb = W2[c * 64 + 32 + lane];
                float v = fmaf(s1, wa.x, fmaf(c1, wa.y,
                          fmaf(s2, wb.x, c2 * wb.y)));
                #pragma unroll
                for (int o = 16; o > 0; o >>= 1)
                    v += __shfl_down_sync(0xffffffffu, v, o);
                if (lane == 0) d_E[pos * CC + c] = v;
            }
        }
    } else {
        // ---- lengths: last-nonzero index per row, then exclusive prefix sum
        __shared__ int s_len[BB];
        int b = tid >> 2;            // 4 threads per row
        int k = tid & 3;
        const int4* row4 = (const int4*)(dates + b * TMAX);
        int last = -1;
        #pragma unroll
        for (int i = 0; i < 16; ++i) {
            int idx = k + i * 4;     // int4 index (i ascending => keep max)
            int4 v = row4[idx];
            int bt = idx * 4;
            if (v.x != 0) last = bt;
            if (v.y != 0) last = bt + 1;
            if (v.z != 0) last = bt + 2;
            if (v.w != 0) last = bt + 3;
        }
        last = max(last, __shfl_down_sync(0xffffffffu, last, 2, 4));
        last = max(last, __shfl_down_sync(0xffffffffu, last, 1, 4));
        if (k == 0) {
            int L = (last < 0) ? (TMAX - 1) : last;
            s_len[b] = L;
            d_len[b] = L;
        }
        __syncthreads();
        if (tid == 0) {
            int acc = 0;
            #pragma unroll
            for (int i = 0; i < BB; ++i) { d_off[i] = acc; acc += s_len[i]; }
            d_off[BB] = acc;
        }
    }

    // Signal PDL: this block's setup stores are issued.
    cudaTriggerProgrammaticLaunchCompletion();
}

// ---------------------------------------------------------------------------
// Write kernel (R4 shape — at the chip store ceiling). Launched with PDL:
// prologue runs concurrently with k_setup; dependent reads after
// cudaGridDependencySynchronize().
// ---------------------------------------------------------------------------
#define TCHUNK 32

__global__ void __launch_bounds__(320) k_write(const int* __restrict__ dates,
                                               float* __restrict__ out) {
    __shared__ int s_dates[TCHUNK];
    int b  = blockIdx.y;
    int t0 = blockIdx.x * TCHUNK;

    int tid  = threadIdx.x;              // 0..319
    int slot = tid >= 160 ? 1 : 0;       // token parity slot (warps 0-4 / 5-9)
    int r    = tid - slot * 160;         // 0..159
    int c    = r >> 4;                   // 0..9
    int p4   = r & 15;                   // 0..15

    // Independent prologue: prefetch dates (input tensor, not setup output).
    if (tid < TCHUNK) s_dates[tid] = __ldg(&dates[b * TMAX + t0 + tid]);

    // Wait for k_setup's grid (full memory visibility guaranteed).
    cudaGridDependencySynchronize();
    __syncthreads();

    int L = d_len[b];
    if (t0 >= L) return;                 // uniform per block

    int n0   = d_off[b];
    int Ntot = d_off[BB];

    float4 y = d_Y4[(b * CC + c) * (PP / 4) + p4];
    float4* out4 = (float4*)out;
    size_t mask_base = (size_t)Ntot * (CC * PP);

    #pragma unroll 4
    for (int i = 0; i < TCHUNK / 2; ++i) {
        int t = t0 + 2 * i + slot;
        if (t >= L) continue;
        int date = s_dates[2 * i + slot];
        float e = __ldg(&d_E[date * CC + c]);
        int n = n0 + t;
        out4[(size_t)n * 160 + r] =
            make_float4(y.x + e, y.y + e, y.z + e, y.w + e);
        if (r < 2)
            out[mask_base + (size_t)n * 2 + r] = (r == 0) ? (float)b : (float)t;
    }
}

// ---------------------------------------------------------------------------
extern "C" void kernel_launch(void* const* d_in, const int* in_sizes, int n_in,
                              void* d_out, int out_size) {
    const float* x     = (const float*)d_in[0];
    // d_in[1] = attentions (unused by the reference computation)
    const int*   dates = (const int*)d_in[2];
    const float* W     = (const float*)d_in[3];
    const float* bias  = (const float*)d_in[4];
    float* out = (float*)d_out;

    k_setup<<<NB_SETUP, 256>>>(x, dates, W, bias);

    // k_write with programmatic dependent launch.
    cudaLaunchConfig_t cfg = {};
    cfg.gridDim  = dim3(TMAX / TCHUNK, BB, 1);
    cfg.blockDim = dim3(320, 1, 1);
    cfg.dynamicSmemBytes = 0;
    cfg.stream = 0;
    cudaLaunchAttribute attrs[1];
    attrs[0].id = cudaLaunchAttributeProgrammaticStreamSerialization;
    attrs[0].val.programmaticStreamSerializationAllowed = 1;
    cfg.attrs = attrs;
    cfg.numAttrs = 1;
    cudaLaunchKernelEx(&cfg, k_write, dates, out);
}